// round 4
// baseline (speedup 1.0000x reference)
#include <cuda_runtime.h>
#include <math.h>

// Sinkhorn distance, B=4, P=2048, D=64, eps=0.1, max_iter=100, thresh=0.1
// Output layout: [cost(4) | pi(4*2048*2048) | C(4*2048*2048)]
// Persistent-kernel design: the 100-iteration loop runs inside ONE kernel
// with a software grid barrier (128 co-resident blocks), breaking early at
// convergence.

#define BB 4
#define PP 2048
#define DD 64
#define NROWS (BB*PP)                 // 8192
#define NEL ((size_t)BB*PP*PP)        // 16777216
#define S_CONST 14.426950408889634f   // (1/eps) * log2(e), eps = 0.1
#define EPSLN2  0.069314718055994531f // eps * ln2
#define NBLK 128
#define NTHR 1024

__device__ float g_u[NROWS];
__device__ float g_v[NROWS];
__device__ float g_err[NROWS];
__device__ float g_xn[NROWS];
__device__ float g_yn[NROWS];
__device__ float g_part[NROWS];
__device__ unsigned g_bar;
__device__ int g_conv;

// Hardware exp2 on the MUFU pipe.
__device__ __forceinline__ float ex2(float x) {
    float r;
    asm("ex2.approx.ftz.f32 %0, %1;" : "=f"(r) : "f"(x));
    return r;
}

// Branchless online LSE step: one MUFU + a few fixed-lat ops, no branch.
__device__ __forceinline__ void olse(float& m, float& s, float a) {
    float e = ex2(0.0f - fabsf(m - a));          // ex2(-|m-a|)
    s = (a > m) ? fmaf(s, e, 1.0f) : (s + e);
    m = fmaxf(m, a);
}

// merge two (max, sum) log2-domain accumulators
__device__ __forceinline__ void lse_merge(float& m, float& s, float m2, float s2) {
    float M = fmaxf(m, m2);
    s = fmaf(s, ex2(m - M), s2 * ex2(m2 - M));
    m = M;
}

// Software grid barrier: monotone counter, deterministic.
__device__ __forceinline__ void gridsync() {
    __syncthreads();
    if (threadIdx.x == 0) {
        __threadfence();
        unsigned old = atomicAdd(&g_bar, 1u);
        unsigned target = (old / NBLK + 1u) * NBLK;
        while (__ldcg((const unsigned*)&g_bar) < target) __nanosleep(32);
    }
    __syncthreads();
}

__global__ void kInit() {
    int t = blockIdx.x * 256 + threadIdx.x;
    if (t < NROWS) { g_u[t] = 0.0f; g_v[t] = 0.0f; }
    if (t == 0) { g_bar = 0u; g_conv = 0; }
}

// Row norms of x and y. One warp per row.
__global__ void kNorm(const float* __restrict__ x, const float* __restrict__ y) {
    int lane = threadIdx.x & 31;
    int gw = blockIdx.x * 8 + (threadIdx.x >> 5);
    const float* src = (gw < NROWS) ? x : y;
    float* dst = (gw < NROWS) ? g_xn : g_yn;
    int row = gw & (NROWS - 1);
    float2 v = ((const float2*)src)[row * 32 + lane];
    float s = fmaf(v.x, v.x, v.y * v.y);
    #pragma unroll
    for (int off = 16; off > 0; off >>= 1)
        s += __shfl_xor_sync(0xffffffffu, s, off);
    if (lane == 0) dst[row] = s;
}

// C[b,i,j] = ||x_i||^2 + ||y_j||^2 - 2 x_i . y_j
__global__ __launch_bounds__(256) void kC(const float* __restrict__ x,
                                          const float* __restrict__ y,
                                          float* __restrict__ Cout) {
    __shared__ float xs[64][68];
    __shared__ float ys[64][68];
    int b  = blockIdx.z;
    int i0 = blockIdx.y * 64;
    int j0 = blockIdx.x * 64;
    for (int idx = threadIdx.x; idx < 64 * 64; idx += 256) {
        int i = idx >> 6, d = idx & 63;
        xs[d][i] = x[((size_t)(b * PP + i0 + i)) * DD + d];
        ys[d][i] = y[((size_t)(b * PP + j0 + i)) * DD + d];
    }
    __syncthreads();
    int tx = threadIdx.x & 15, ty = threadIdx.x >> 4;
    float acc[4][4] = {};
    #pragma unroll 16
    for (int d = 0; d < 64; d++) {
        float4 xv = *(const float4*)&xs[d][ty * 4];
        float4 yv = *(const float4*)&ys[d][tx * 4];
        acc[0][0] = fmaf(xv.x, yv.x, acc[0][0]);
        acc[0][1] = fmaf(xv.x, yv.y, acc[0][1]);
        acc[0][2] = fmaf(xv.x, yv.z, acc[0][2]);
        acc[0][3] = fmaf(xv.x, yv.w, acc[0][3]);
        acc[1][0] = fmaf(xv.y, yv.x, acc[1][0]);
        acc[1][1] = fmaf(xv.y, yv.y, acc[1][1]);
        acc[1][2] = fmaf(xv.y, yv.z, acc[1][2]);
        acc[1][3] = fmaf(xv.y, yv.w, acc[1][3]);
        acc[2][0] = fmaf(xv.z, yv.x, acc[2][0]);
        acc[2][1] = fmaf(xv.z, yv.y, acc[2][1]);
        acc[2][2] = fmaf(xv.z, yv.z, acc[2][2]);
        acc[2][3] = fmaf(xv.z, yv.w, acc[2][3]);
        acc[3][0] = fmaf(xv.w, yv.x, acc[3][0]);
        acc[3][1] = fmaf(xv.w, yv.y, acc[3][1]);
        acc[3][2] = fmaf(xv.w, yv.z, acc[3][2]);
        acc[3][3] = fmaf(xv.w, yv.w, acc[3][3]);
    }
    int gi = b * PP + i0 + ty * 4;
    int gj = b * PP + j0 + tx * 4;
    float xn[4] = {g_xn[gi], g_xn[gi + 1], g_xn[gi + 2], g_xn[gi + 3]};
    float yn[4] = {g_yn[gj], g_yn[gj + 1], g_yn[gj + 2], g_yn[gj + 3]};
    #pragma unroll
    for (int r = 0; r < 4; r++) {
        float4 o;
        o.x = fmaf(-2.0f, acc[r][0], xn[r] + yn[0]);
        o.y = fmaf(-2.0f, acc[r][1], xn[r] + yn[1]);
        o.z = fmaf(-2.0f, acc[r][2], xn[r] + yn[2]);
        o.w = fmaf(-2.0f, acc[r][3], xn[r] + yn[3]);
        ((float4*)(Cout + ((size_t)(b * PP + i0 + ty * 4 + r)) * PP + j0))[tx] = o;
    }
}

// Persistent Sinkhorn loop + final pi/cost.
// 128 blocks x 1024 threads, all co-resident. Block handles 64 consecutive
// rows (phase U / final) and 2 column stripes of 32 cols (phase V).
__global__ __launch_bounds__(NTHR, 1) void kSink(const float* __restrict__ C,
                                                 float* __restrict__ pi,
                                                 float* __restrict__ cost,
                                                 float eps_log_mu,
                                                 float thresh_tot) {
    __shared__ __align__(16) float sv[PP];
    __shared__ float smm[2][16][32];
    __shared__ float sms[2][16][32];
    __shared__ float red[NTHR];
    int tid = threadIdx.x;
    int w = tid >> 5, lane = tid & 31;
    int blk = blockIdx.x;
    int b = blk >> 5;                      // batch (32 blocks per batch)
    int r0 = blk * 64;                     // first row of this block
    const float4* sv4 = (const float4*)sv;

    for (int it = 0; it < 100; it++) {
        // ================= phase U: per-row LSE over j =================
        {
            const float4* vb = ((const float4*)g_v) + b * (PP / 4);
            for (int t = tid; t < PP / 4; t += NTHR) {
                float4 v = __ldcg(vb + t);
                v.x *= S_CONST; v.y *= S_CONST; v.z *= S_CONST; v.w *= S_CONST;
                ((float4*)sv)[t] = v;
            }
        }
        __syncthreads();
        #pragma unroll
        for (int rr = 0; rr < 2; rr++) {
            int row = r0 + 2 * w + rr;
            const float4* Crow = (const float4*)(C + (size_t)row * PP);
            float m0 = -INFINITY, m1 = -INFINITY, m2 = -INFINITY, m3 = -INFINITY;
            float s0 = 0.0f, s1 = 0.0f, s2 = 0.0f, s3 = 0.0f;
            #pragma unroll
            for (int k = 0; k < 16; k++) {
                int idx = lane + k * 32;
                float4 c4 = Crow[idx];
                float4 v4 = sv4[idx];
                olse(m0, s0, fmaf(c4.x, -S_CONST, v4.x));
                olse(m1, s1, fmaf(c4.y, -S_CONST, v4.y));
                olse(m2, s2, fmaf(c4.z, -S_CONST, v4.z));
                olse(m3, s3, fmaf(c4.w, -S_CONST, v4.w));
            }
            lse_merge(m0, s0, m1, s1);
            lse_merge(m2, s2, m3, s3);
            lse_merge(m0, s0, m2, s2);
            #pragma unroll
            for (int off = 16; off > 0; off >>= 1) {
                float mo = __shfl_xor_sync(0xffffffffu, m0, off);
                float so = __shfl_xor_sync(0xffffffffu, s0, off);
                lse_merge(m0, s0, mo, so);
            }
            if (lane == 0) {
                float lse2 = m0 + __log2f(s0);
                float un = fmaf(-EPSLN2, lse2, eps_log_mu);
                float old = __ldcg(&g_u[row]);
                g_u[row] = un;
                g_err[row] = fabsf(un - old);
            }
        }
        gridsync();

        // ================= phase V: per-col LSE over i =================
        {
            const float4* ub = ((const float4*)g_u) + b * (PP / 4);
            for (int t = tid; t < PP / 4; t += NTHR) {
                float4 u4 = __ldcg(ub + t);
                u4.x *= S_CONST; u4.y *= S_CONST; u4.z *= S_CONST; u4.w *= S_CONST;
                ((float4*)sv)[t] = u4;
            }
        }
        __syncthreads();
        {
            int sh = w >> 4;                       // stripe half (0/1)
            int wl = w & 15;                       // warp within stripe
            int j0 = ((blk * 2 + sh) & 63) * 32;
            const float* pa = C + (size_t)b * PP * PP + (size_t)(wl * 128) * PP + j0 + lane;
            const float* pb = pa + (size_t)64 * PP;
            const float* ur = sv + wl * 128;
            float ma = -INFINITY, sa = 0.0f, mb = -INFINITY, sb = 0.0f;
            #pragma unroll 8
            for (int r = 0; r < 64; r++) {
                float ca = *pa; pa += PP;
                float cb = *pb; pb += PP;
                olse(ma, sa, fmaf(ca, -S_CONST, ur[r]));
                olse(mb, sb, fmaf(cb, -S_CONST, ur[r + 64]));
            }
            lse_merge(ma, sa, mb, sb);
            smm[sh][wl][lane] = ma;
            sms[sh][wl][lane] = sa;
        }
        __syncthreads();
        if (tid < 64) {
            int sh2 = tid >> 5, l2 = tid & 31;
            float M = smm[sh2][0][l2], SS = sms[sh2][0][l2];
            #pragma unroll
            for (int k = 1; k < 16; k++)
                lse_merge(M, SS, smm[sh2][k][l2], sms[sh2][k][l2]);
            float lse2 = M + __log2f(SS);
            int jj0 = ((blk * 2 + sh2) & 63) * 32;
            g_v[b * PP + jj0 + l2] = fmaf(-EPSLN2, lse2, eps_log_mu);
        }

        // convergence check (block 0, deterministic fixed-order reduction)
        if (blk == 0) {
            __syncthreads();
            float ts = 0.0f;
            #pragma unroll
            for (int k = 0; k < NROWS / NTHR; k++)
                ts += __ldcg(&g_err[tid + k * NTHR]);
            red[tid] = ts;
            __syncthreads();
            for (int st = 512; st > 0; st >>= 1) {
                if (tid < st) red[tid] += red[tid + st];
                __syncthreads();
            }
            if (tid == 0 && red[0] < thresh_tot) g_conv = 1;
        }
        gridsync();
        if (__ldcg(&g_conv)) break;
    }

    // ================= final: pi = exp2((u+v-C)*S), cost partials =========
    {
        const float4* vb = ((const float4*)g_v) + b * (PP / 4);
        for (int t = tid; t < PP / 4; t += NTHR) {
            float4 v = __ldcg(vb + t);
            v.x *= S_CONST; v.y *= S_CONST; v.z *= S_CONST; v.w *= S_CONST;
            ((float4*)sv)[t] = v;
        }
    }
    __syncthreads();
    #pragma unroll
    for (int rr = 0; rr < 2; rr++) {
        int row = r0 + 2 * w + rr;
        float uiS = __ldcg(&g_u[row]) * S_CONST;
        const float4* Crow = (const float4*)(C + (size_t)row * PP);
        float4* prow = (float4*)(pi + (size_t)row * PP);
        float local = 0.0f;
        #pragma unroll
        for (int k = 0; k < 16; k++) {
            int idx = lane + k * 32;
            float4 c4 = Crow[idx];
            float4 v4 = sv4[idx];
            float4 p4;
            p4.x = ex2(fmaf(c4.x, -S_CONST, uiS + v4.x));
            p4.y = ex2(fmaf(c4.y, -S_CONST, uiS + v4.y));
            p4.z = ex2(fmaf(c4.z, -S_CONST, uiS + v4.z));
            p4.w = ex2(fmaf(c4.w, -S_CONST, uiS + v4.w));
            prow[idx] = p4;
            local = fmaf(p4.x, c4.x, local);
            local = fmaf(p4.y, c4.y, local);
            local = fmaf(p4.z, c4.z, local);
            local = fmaf(p4.w, c4.w, local);
        }
        #pragma unroll
        for (int off = 16; off > 0; off >>= 1)
            local += __shfl_xor_sync(0xffffffffu, local, off);
        if (lane == 0) g_part[row] = local;
    }
    gridsync();
    if (blk == 0) {
        for (int bb = 0; bb < BB; bb++) {
            float t = __ldcg(&g_part[bb * PP + tid]) +
                      __ldcg(&g_part[bb * PP + tid + NTHR]);
            red[tid] = t;
            __syncthreads();
            for (int st = 512; st > 0; st >>= 1) {
                if (tid < st) red[tid] += red[tid + st];
                __syncthreads();
            }
            if (tid == 0) cost[bb] = red[0];
            __syncthreads();
        }
    }
}

extern "C" void kernel_launch(void* const* d_in, const int* in_sizes, int n_in,
                              void* d_out, int out_size) {
    const float* x = (const float*)d_in[0];
    const float* y = (const float*)d_in[1];
    float* out  = (float*)d_out;
    float* cost = out;                        // 4
    float* pi   = out + 4;                    // 16777216
    float* C    = out + 4 + (size_t)NEL;      // 16777216

    float log_mu = logf(1.0f / 2048.0f + 1e-8f);   // == log_nu (P1==P2)
    float eps_log_mu = 0.1f * log_mu;
    float thresh_tot = 0.1f * (float)BB;           // global-sum form of err<0.1

    kInit<<<(NROWS + 255) / 256, 256>>>();
    kNorm<<<2 * NROWS / 8, 256>>>(x, y);
    dim3 gC(PP / 64, PP / 64, BB);
    kC<<<gC, 256>>>(x, y, C);
    kSink<<<NBLK, NTHR>>>(C, pi, cost, eps_log_mu, thresh_tot);
}

// round 5
// speedup vs baseline: 2.1468x; 2.1468x over previous
#include <cuda_runtime.h>
#include <math.h>

// Sinkhorn distance, B=4, P=2048, D=64, eps=0.1, max_iter=100, thresh=0.1
// Output layout: [cost(4) | pi(4*2048*2048) | C(4*2048*2048)]
// Fused iteration: kUV reads C ONCE per iteration (row LSE -> u update ->
// column partial LSE from the smem-staged av matrix); kMerge folds column
// partials into v and updates the convergence flag.

#define BB 4
#define PP 2048
#define DD 64
#define NROWS (BB*PP)                 // 8192
#define NEL ((size_t)BB*PP*PP)        // 16777216
#define S_CONST 14.426950408889634f   // (1/eps) * log2(e), eps = 0.1
#define EPSLN2  0.069314718055994531f // eps * ln2
#define ROWS_PB 16
#define UVBLKS (NROWS/ROWS_PB)        // 512
#define PBLKS  (PP/ROWS_PB)           // 128 partial blocks per batch

__device__ float g_u[NROWS];
__device__ float g_v[NROWS];
__device__ float g_err[NROWS];
__device__ float g_xn[NROWS];
__device__ float g_yn[NROWS];
__device__ float g_part[NROWS];
__device__ int   g_done[104];
__device__ float g_pm[UVBLKS * PP];   // column-max partials, 4MB
__device__ float g_ps[UVBLKS * PP];   // column-sum partials, 4MB

// Hardware exp2 on the MUFU pipe.
__device__ __forceinline__ float ex2(float x) {
    float r;
    asm("ex2.approx.ftz.f32 %0, %1;" : "=f"(r) : "f"(x));
    return r;
}

// Branchless online LSE step (log2 domain).
__device__ __forceinline__ void olse(float& m, float& s, float a) {
    float e = ex2(0.0f - fabsf(m - a));
    s = (a > m) ? fmaf(s, e, 1.0f) : (s + e);
    m = fmaxf(m, a);
}

// Merge two (max, sum) log2-domain accumulators. Handles m==-INF (s==0).
__device__ __forceinline__ void lse_merge(float& m, float& s, float m2, float s2) {
    float M = fmaxf(m, m2);
    s = fmaf(s, ex2(m - M), s2 * ex2(m2 - M));
    m = M;
}

__global__ void kInit() {
    int t = blockIdx.x * 256 + threadIdx.x;
    if (t < NROWS) { g_u[t] = 0.0f; g_v[t] = 0.0f; }
    if (t == 0) g_done[0] = 0;
}

// Row norms. One warp per row.
__global__ void kNorm(const float* __restrict__ x, const float* __restrict__ y) {
    int lane = threadIdx.x & 31;
    int gw = blockIdx.x * 8 + (threadIdx.x >> 5);
    const float* src = (gw < NROWS) ? x : y;
    float* dst = (gw < NROWS) ? g_xn : g_yn;
    int row = gw & (NROWS - 1);
    float2 v = ((const float2*)src)[row * 32 + lane];
    float s = fmaf(v.x, v.x, v.y * v.y);
    #pragma unroll
    for (int off = 16; off > 0; off >>= 1)
        s += __shfl_xor_sync(0xffffffffu, s, off);
    if (lane == 0) dst[row] = s;
}

// C[b,i,j] = ||x_i||^2 + ||y_j||^2 - 2 x_i . y_j
__global__ __launch_bounds__(256) void kC(const float* __restrict__ x,
                                          const float* __restrict__ y,
                                          float* __restrict__ Cout) {
    __shared__ float xs[64][68];
    __shared__ float ys[64][68];
    int b  = blockIdx.z;
    int i0 = blockIdx.y * 64;
    int j0 = blockIdx.x * 64;
    for (int idx = threadIdx.x; idx < 64 * 64; idx += 256) {
        int i = idx >> 6, d = idx & 63;
        xs[d][i] = x[((size_t)(b * PP + i0 + i)) * DD + d];
        ys[d][i] = y[((size_t)(b * PP + j0 + i)) * DD + d];
    }
    __syncthreads();
    int tx = threadIdx.x & 15, ty = threadIdx.x >> 4;
    float acc[4][4] = {};
    #pragma unroll 16
    for (int d = 0; d < 64; d++) {
        float4 xv = *(const float4*)&xs[d][ty * 4];
        float4 yv = *(const float4*)&ys[d][tx * 4];
        acc[0][0] = fmaf(xv.x, yv.x, acc[0][0]);
        acc[0][1] = fmaf(xv.x, yv.y, acc[0][1]);
        acc[0][2] = fmaf(xv.x, yv.z, acc[0][2]);
        acc[0][3] = fmaf(xv.x, yv.w, acc[0][3]);
        acc[1][0] = fmaf(xv.y, yv.x, acc[1][0]);
        acc[1][1] = fmaf(xv.y, yv.y, acc[1][1]);
        acc[1][2] = fmaf(xv.y, yv.z, acc[1][2]);
        acc[1][3] = fmaf(xv.y, yv.w, acc[1][3]);
        acc[2][0] = fmaf(xv.z, yv.x, acc[2][0]);
        acc[2][1] = fmaf(xv.z, yv.y, acc[2][1]);
        acc[2][2] = fmaf(xv.z, yv.z, acc[2][2]);
        acc[2][3] = fmaf(xv.z, yv.w, acc[2][3]);
        acc[3][0] = fmaf(xv.w, yv.x, acc[3][0]);
        acc[3][1] = fmaf(xv.w, yv.y, acc[3][1]);
        acc[3][2] = fmaf(xv.w, yv.z, acc[3][2]);
        acc[3][3] = fmaf(xv.w, yv.w, acc[3][3]);
    }
    int gi = b * PP + i0 + ty * 4;
    int gj = b * PP + j0 + tx * 4;
    float xn[4] = {g_xn[gi], g_xn[gi + 1], g_xn[gi + 2], g_xn[gi + 3]};
    float yn[4] = {g_yn[gj], g_yn[gj + 1], g_yn[gj + 2], g_yn[gj + 3]};
    #pragma unroll
    for (int r = 0; r < 4; r++) {
        float4 o;
        o.x = fmaf(-2.0f, acc[r][0], xn[r] + yn[0]);
        o.y = fmaf(-2.0f, acc[r][1], xn[r] + yn[1]);
        o.z = fmaf(-2.0f, acc[r][2], xn[r] + yn[2]);
        o.w = fmaf(-2.0f, acc[r][3], xn[r] + yn[3]);
        ((float4*)(Cout + ((size_t)(b * PP + i0 + ty * 4 + r)) * PP + j0))[tx] = o;
    }
}

// Fused U+column-partial kernel. 512 blocks x 1024 threads.
// Block = 16 rows x 2048 cols of one batch. Reads C once:
//  1) load row tile, compute av=(v-C)*S into smem, online row LSE -> u_new
//  2) column pass over smem av: accumulate per-column (max,sum) partials
//     of (u_new - C)*S = av + uS_new - vS.
__global__ __launch_bounds__(1024, 1) void kUV(const float* __restrict__ C,
                                               int it, float eps_log_mu) {
    if (g_done[it]) return;
    extern __shared__ float smem[];
    float* vsm  = smem;                        // 2048  (v * S)
    float* av   = smem + PP;                   // 16 * 2048
    float* wm   = av + ROWS_PB * PP;           // 32
    float* ws   = wm + 32;                     // 32
    float* urow = ws + 32;                     // 16  (u_new * S)

    int tid = threadIdx.x;
    int blk = blockIdx.x;
    int b   = blk >> 7;                        // batch
    int p   = blk & (PBLKS - 1);               // row-group within batch
    int row0 = b * PP + p * ROWS_PB;

    const float4* vb = (const float4*)(g_v + b * PP);
    for (int t = tid; t < PP / 4; t += 1024) {
        float4 v = vb[t];
        v.x *= S_CONST; v.y *= S_CONST; v.z *= S_CONST; v.w *= S_CONST;
        ((float4*)vsm)[t] = v;
    }
    __syncthreads();

    int w = tid >> 5, lane = tid & 31;
    int r = w >> 1, h = w & 1;                 // 2 warps per row
    int row = row0 + r;
    const float4* Crow = (const float4*)(C + (size_t)row * PP);
    const float4* vsm4 = (const float4*)vsm;
    float4* av4 = (float4*)(av + r * PP);

    float m0 = -INFINITY, m1 = -INFINITY, m2 = -INFINITY, m3 = -INFINITY;
    float s0 = 0.0f, s1 = 0.0f, s2 = 0.0f, s3 = 0.0f;
    #pragma unroll
    for (int k = 0; k < 8; k++) {
        int j4 = h * 256 + k * 32 + lane;
        float4 c4 = Crow[j4];
        float4 vv = vsm4[j4];
        float4 a;
        a.x = fmaf(c4.x, -S_CONST, vv.x);
        a.y = fmaf(c4.y, -S_CONST, vv.y);
        a.z = fmaf(c4.z, -S_CONST, vv.z);
        a.w = fmaf(c4.w, -S_CONST, vv.w);
        av4[j4] = a;
        olse(m0, s0, a.x);
        olse(m1, s1, a.y);
        olse(m2, s2, a.z);
        olse(m3, s3, a.w);
    }
    lse_merge(m0, s0, m1, s1);
    lse_merge(m2, s2, m3, s3);
    lse_merge(m0, s0, m2, s2);
    #pragma unroll
    for (int off = 16; off > 0; off >>= 1) {
        float mo = __shfl_xor_sync(0xffffffffu, m0, off);
        float so = __shfl_xor_sync(0xffffffffu, s0, off);
        lse_merge(m0, s0, mo, so);
    }
    if (lane == 0) { wm[w] = m0; ws[w] = s0; }
    __syncthreads();
    if (tid < ROWS_PB) {
        float M = wm[2 * tid], S = ws[2 * tid];
        lse_merge(M, S, wm[2 * tid + 1], ws[2 * tid + 1]);
        float lse2 = M + __log2f(S);
        float un = fmaf(-EPSLN2, lse2, eps_log_mu);
        int rw = row0 + tid;
        float old = g_u[rw];
        g_u[rw] = un;
        g_err[rw] = fabsf(un - old);
        urow[tid] = un * S_CONST;
    }
    __syncthreads();

    // column pass: thread owns 2 columns
    int j = tid * 2;
    float vs0 = vsm[j], vs1 = vsm[j + 1];
    float mc0 = -INFINITY, sc0 = 0.0f, mc1 = -INFINITY, sc1 = 0.0f;
    #pragma unroll
    for (int rr = 0; rr < ROWS_PB; rr++) {
        float uS = urow[rr];
        float2 a2 = *(const float2*)(av + rr * PP + j);
        olse(mc0, sc0, a2.x + (uS - vs0));
        olse(mc1, sc1, a2.y + (uS - vs1));
    }
    size_t pb = (size_t)blk * PP + j;
    *(float2*)(g_pm + pb) = make_float2(mc0, mc1);
    *(float2*)(g_ps + pb) = make_float2(sc0, sc1);
}

// Merge column partials -> v update; block 0 also updates the done flag.
// 64 blocks x 128 threads; thread owns one column, folds 128 partials
// in fixed order (deterministic).
__global__ __launch_bounds__(128) void kMerge(int it, float eps_log_nu,
                                              float thresh_tot) {
    __shared__ float red[128];
    int done = g_done[it];
    int t = threadIdx.x;
    int mblk = blockIdx.x;
    if (!done) {
        int b = mblk >> 4;
        int j = (mblk & 15) * 128 + t;
        const float* pm = g_pm + (size_t)(b * PBLKS) * PP + j;
        const float* ps = g_ps + (size_t)(b * PBLKS) * PP + j;
        float M = -INFINITY, S = 0.0f;
        #pragma unroll 4
        for (int p = 0; p < PBLKS; p++) {
            lse_merge(M, S, pm[(size_t)p * PP], ps[(size_t)p * PP]);
        }
        float lse2 = M + __log2f(S);
        g_v[b * PP + j] = fmaf(-EPSLN2, lse2, eps_log_nu);
    }
    if (mblk == 0) {
        if (done) {
            if (t == 0) g_done[it + 1] = 1;
            return;
        }
        float ts = 0.0f;
        #pragma unroll
        for (int k = 0; k < NROWS / 128; k++)
            ts += g_err[t + k * 128];
        red[t] = ts;
        __syncthreads();
        for (int st = 64; st > 0; st >>= 1) {
            if (t < st) red[t] += red[t + st];
            __syncthreads();
        }
        if (t == 0) g_done[it + 1] = (red[0] < thresh_tot) ? 1 : 0;
    }
}

// pi = exp2((u+v-C)*S); per-row partial of sum(pi*C)
__global__ __launch_bounds__(256) void kFinal(const float* __restrict__ C,
                                              float* __restrict__ pi) {
    __shared__ __align__(16) float ws[PP];
    __shared__ float red[256];
    int row = blockIdx.x;
    int b = row >> 11;
    float ui = g_u[row];
    const float4* vb = (const float4*)(g_v + b * PP);
    for (int t = threadIdx.x; t < PP / 4; t += 256) {
        float4 v4 = vb[t];
        v4.x = (ui + v4.x) * S_CONST;
        v4.y = (ui + v4.y) * S_CONST;
        v4.z = (ui + v4.z) * S_CONST;
        v4.w = (ui + v4.w) * S_CONST;
        ((float4*)ws)[t] = v4;
    }
    __syncthreads();
    const float4* Crow = (const float4*)(C + (size_t)row * PP);
    float4* prow = (float4*)(pi + (size_t)row * PP);
    const float4* ws4 = (const float4*)ws;
    float local = 0.0f;
    #pragma unroll
    for (int k = 0; k < 2; k++) {
        int idx = threadIdx.x + k * 256;
        float4 c4 = Crow[idx];
        float4 w4 = ws4[idx];
        float4 p4;
        p4.x = ex2(fmaf(c4.x, -S_CONST, w4.x));
        p4.y = ex2(fmaf(c4.y, -S_CONST, w4.y));
        p4.z = ex2(fmaf(c4.z, -S_CONST, w4.z));
        p4.w = ex2(fmaf(c4.w, -S_CONST, w4.w));
        prow[idx] = p4;
        local = fmaf(p4.x, c4.x, local);
        local = fmaf(p4.y, c4.y, local);
        local = fmaf(p4.z, c4.z, local);
        local = fmaf(p4.w, c4.w, local);
    }
    red[threadIdx.x] = local;
    __syncthreads();
    for (int st = 128; st > 0; st >>= 1) {
        if (threadIdx.x < st) red[threadIdx.x] += red[threadIdx.x + st];
        __syncthreads();
    }
    if (threadIdx.x == 0) g_part[row] = red[0];
}

__global__ void kCost(float* __restrict__ cost) {
    __shared__ float red[256];
    int b = blockIdx.x;
    float t = 0.0f;
    #pragma unroll
    for (int k = 0; k < 8; k++)
        t += g_part[b * 2048 + threadIdx.x + k * 256];
    red[threadIdx.x] = t;
    __syncthreads();
    for (int st = 128; st > 0; st >>= 1) {
        if (threadIdx.x < st) red[threadIdx.x] += red[threadIdx.x + st];
        __syncthreads();
    }
    if (threadIdx.x == 0) cost[b] = red[0];
}

extern "C" void kernel_launch(void* const* d_in, const int* in_sizes, int n_in,
                              void* d_out, int out_size) {
    const float* x = (const float*)d_in[0];
    const float* y = (const float*)d_in[1];
    float* out  = (float*)d_out;
    float* cost = out;                        // 4
    float* pi   = out + 4;                    // 16777216
    float* C    = out + 4 + (size_t)NEL;      // 16777216

    float log_mu = logf(1.0f / 2048.0f + 1e-8f);   // == log_nu (P1==P2)
    float eps_log_mu = 0.1f * log_mu;
    float thresh_tot = 0.1f * (float)BB;           // global-sum form of err<0.1

    const int kuv_smem = (PP + ROWS_PB * PP + 32 + 32 + 16) * 4;  // ~136KB
    static int attr_set = 0;
    if (!attr_set) {
        cudaFuncSetAttribute(kUV, cudaFuncAttributeMaxDynamicSharedMemorySize,
                             kuv_smem);
        attr_set = 1;
    }

    kInit<<<(NROWS + 255) / 256, 256>>>();
    kNorm<<<2 * NROWS / 8, 256>>>(x, y);
    dim3 gC(PP / 64, PP / 64, BB);
    kC<<<gC, 256>>>(x, y, C);
    for (int it = 0; it < 100; it++) {
        kUV<<<UVBLKS, 1024, kuv_smem>>>(C, it, eps_log_mu);
        kMerge<<<64, 128>>>(it, eps_log_mu, thresh_tot);
    }
    kFinal<<<NROWS, 256>>>(C, pi);
    kCost<<<BB, 256>>>(cost);
}

// round 6
// speedup vs baseline: 2.2599x; 1.0527x over previous
#include <cuda_runtime.h>
#include <math.h>

// Sinkhorn distance, B=4, P=2048, D=64, eps=0.1, max_iter=100, thresh=0.1
// Output layout: [cost(4) | pi(4*2048*2048) | C(4*2048*2048)]
// One fused kernel per iteration: reads C once, computes row LSE -> u update,
// column (max,sum) partials, and the last-arriving blocks (atomic ticket)
// merge partials into v and update the convergence flag. No separate merge
// kernel.

#define BB 4
#define PP 2048
#define DD 64
#define NROWS (BB*PP)                 // 8192
#define NEL ((size_t)BB*PP*PP)        // 16777216
#define S_CONST 14.426950408889634f   // (1/eps) * log2(e), eps = 0.1
#define EPSLN2  0.069314718055994531f // eps * ln2
#define ROWS_PB 16
#define UVBLKS (NROWS/ROWS_PB)        // 512
#define PBLKS  (PP/ROWS_PB)           // 128 blocks per batch
#define MSPLIT 4                      // last 4 blocks/batch merge 512 cols each

__device__ float g_u[NROWS];
__device__ float g_v[NROWS];
__device__ float g_err[NROWS];
__device__ float g_xn[NROWS];
__device__ float g_yn[NROWS];
__device__ float g_part[NROWS];
__device__ int   g_done[104];
__device__ float g_pm[UVBLKS * PP];   // column-max partials (4MB)
__device__ float g_ps[UVBLKS * PP];   // column-sum partials (4MB)
__device__ int   g_cntb[100 * BB];    // per-iteration per-batch tickets
__device__ int   g_cnta[100];         // per-iteration global tickets

__device__ __forceinline__ float ex2(float x) {
    float r;
    asm("ex2.approx.ftz.f32 %0, %1;" : "=f"(r) : "f"(x));
    return r;
}

// Merge two (max, sum) log2-domain accumulators. Handles s==0 partials.
__device__ __forceinline__ void lse_merge(float& m, float& s, float m2, float s2) {
    float M = fmaxf(m, m2);
    s = fmaf(s, ex2(m - M), s2 * ex2(m2 - M));
    m = M;
}

__global__ void kInit() {
    int t = blockIdx.x * 256 + threadIdx.x;
    if (t < NROWS) { g_u[t] = 0.0f; g_v[t] = 0.0f; }
    if (t < 100 * BB) g_cntb[t] = 0;
    if (t < 100) g_cnta[t] = 0;
    if (t == 0) g_done[0] = 0;
}

// Row norms. One warp per row.
__global__ void kNorm(const float* __restrict__ x, const float* __restrict__ y) {
    int lane = threadIdx.x & 31;
    int gw = blockIdx.x * 8 + (threadIdx.x >> 5);
    const float* src = (gw < NROWS) ? x : y;
    float* dst = (gw < NROWS) ? g_xn : g_yn;
    int row = gw & (NROWS - 1);
    float2 v = ((const float2*)src)[row * 32 + lane];
    float s = fmaf(v.x, v.x, v.y * v.y);
    #pragma unroll
    for (int off = 16; off > 0; off >>= 1)
        s += __shfl_xor_sync(0xffffffffu, s, off);
    if (lane == 0) dst[row] = s;
}

// C[b,i,j] = ||x_i||^2 + ||y_j||^2 - 2 x_i . y_j
__global__ __launch_bounds__(256) void kC(const float* __restrict__ x,
                                          const float* __restrict__ y,
                                          float* __restrict__ Cout) {
    __shared__ float xs[64][68];
    __shared__ float ys[64][68];
    int b  = blockIdx.z;
    int i0 = blockIdx.y * 64;
    int j0 = blockIdx.x * 64;
    for (int idx = threadIdx.x; idx < 64 * 64; idx += 256) {
        int i = idx >> 6, d = idx & 63;
        xs[d][i] = x[((size_t)(b * PP + i0 + i)) * DD + d];
        ys[d][i] = y[((size_t)(b * PP + j0 + i)) * DD + d];
    }
    __syncthreads();
    int tx = threadIdx.x & 15, ty = threadIdx.x >> 4;
    float acc[4][4] = {};
    #pragma unroll 16
    for (int d = 0; d < 64; d++) {
        float4 xv = *(const float4*)&xs[d][ty * 4];
        float4 yv = *(const float4*)&ys[d][tx * 4];
        acc[0][0] = fmaf(xv.x, yv.x, acc[0][0]);
        acc[0][1] = fmaf(xv.x, yv.y, acc[0][1]);
        acc[0][2] = fmaf(xv.x, yv.z, acc[0][2]);
        acc[0][3] = fmaf(xv.x, yv.w, acc[0][3]);
        acc[1][0] = fmaf(xv.y, yv.x, acc[1][0]);
        acc[1][1] = fmaf(xv.y, yv.y, acc[1][1]);
        acc[1][2] = fmaf(xv.y, yv.z, acc[1][2]);
        acc[1][3] = fmaf(xv.y, yv.w, acc[1][3]);
        acc[2][0] = fmaf(xv.z, yv.x, acc[2][0]);
        acc[2][1] = fmaf(xv.z, yv.y, acc[2][1]);
        acc[2][2] = fmaf(xv.z, yv.z, acc[2][2]);
        acc[2][3] = fmaf(xv.z, yv.w, acc[2][3]);
        acc[3][0] = fmaf(xv.w, yv.x, acc[3][0]);
        acc[3][1] = fmaf(xv.w, yv.y, acc[3][1]);
        acc[3][2] = fmaf(xv.w, yv.z, acc[3][2]);
        acc[3][3] = fmaf(xv.w, yv.w, acc[3][3]);
    }
    int gi = b * PP + i0 + ty * 4;
    int gj = b * PP + j0 + tx * 4;
    float xn[4] = {g_xn[gi], g_xn[gi + 1], g_xn[gi + 2], g_xn[gi + 3]};
    float yn[4] = {g_yn[gj], g_yn[gj + 1], g_yn[gj + 2], g_yn[gj + 3]};
    #pragma unroll
    for (int r = 0; r < 4; r++) {
        float4 o;
        o.x = fmaf(-2.0f, acc[r][0], xn[r] + yn[0]);
        o.y = fmaf(-2.0f, acc[r][1], xn[r] + yn[1]);
        o.z = fmaf(-2.0f, acc[r][2], xn[r] + yn[2]);
        o.w = fmaf(-2.0f, acc[r][3], xn[r] + yn[3]);
        ((float4*)(Cout + ((size_t)(b * PP + i0 + ty * 4 + r)) * PP + j0))[tx] = o;
    }
}

// Fused per-iteration kernel. 512 blocks x 1024 threads, 1 block/SM (136KB smem).
// Block = 16 rows x 2048 cols of one batch.
__global__ __launch_bounds__(1024, 1) void kUV(const float* __restrict__ C,
                                               int it, float eps_log_mu,
                                               float thresh_tot) {
    if (g_done[it]) {
        if (blockIdx.x == 0 && threadIdx.x == 0) g_done[it + 1] = 1;
        return;
    }
    extern __shared__ float smd[];
    float* vsm  = smd;                         // 2048  (v * S)
    float* av   = smd + PP;                    // 16 * 2048
    float* wm   = av + ROWS_PB * PP;           // 32
    float* ws   = wm + 32;                     // 32
    float* urow = ws + 32;                     // 16  (u_new * S)
    __shared__ int s_oldb, s_olda;

    int tid = threadIdx.x;
    int blk = blockIdx.x;
    int b   = blk >> 7;
    int p   = blk & (PBLKS - 1);
    int row0 = b * PP + p * ROWS_PB;

    const float4* vb = (const float4*)(g_v + b * PP);
    for (int t = tid; t < PP / 4; t += 1024) {
        float4 v = vb[t];
        v.x *= S_CONST; v.y *= S_CONST; v.z *= S_CONST; v.w *= S_CONST;
        ((float4*)vsm)[t] = v;
    }
    __syncthreads();

    // ---- row phase: 2 warps per row, av kept in registers ----
    int w = tid >> 5, lane = tid & 31;
    int r = w >> 1, h = w & 1;
    const float4* Crow = (const float4*)(C + (size_t)(row0 + r) * PP);
    const float4* vsm4 = (const float4*)vsm;
    float4* avr = (float4*)(av + r * PP);

    float4 a[8];
    float m0 = -INFINITY, m1 = -INFINITY, m2 = -INFINITY, m3 = -INFINITY;
    #pragma unroll
    for (int k = 0; k < 8; k++) {
        int j4 = h * 256 + k * 32 + lane;
        float4 c4 = Crow[j4];
        float4 vv = vsm4[j4];
        a[k].x = fmaf(c4.x, -S_CONST, vv.x);
        a[k].y = fmaf(c4.y, -S_CONST, vv.y);
        a[k].z = fmaf(c4.z, -S_CONST, vv.z);
        a[k].w = fmaf(c4.w, -S_CONST, vv.w);
        avr[j4] = a[k];
        m0 = fmaxf(m0, a[k].x);
        m1 = fmaxf(m1, a[k].y);
        m2 = fmaxf(m2, a[k].z);
        m3 = fmaxf(m3, a[k].w);
    }
    float m = fmaxf(fmaxf(m0, m1), fmaxf(m2, m3));
    #pragma unroll
    for (int off = 16; off > 0; off >>= 1)
        m = fmaxf(m, __shfl_xor_sync(0xffffffffu, m, off));
    if (lane == 0) wm[w] = m;
    __syncthreads();
    m = fmaxf(wm[2 * r], wm[2 * r + 1]);

    float s0 = 0.0f, s1 = 0.0f, s2 = 0.0f, s3 = 0.0f;
    #pragma unroll
    for (int k = 0; k < 8; k++) {
        s0 += ex2(a[k].x - m);
        s1 += ex2(a[k].y - m);
        s2 += ex2(a[k].z - m);
        s3 += ex2(a[k].w - m);
    }
    float s = (s0 + s1) + (s2 + s3);
    #pragma unroll
    for (int off = 16; off > 0; off >>= 1)
        s += __shfl_xor_sync(0xffffffffu, s, off);
    if (lane == 0) ws[w] = s;
    __syncthreads();
    if (tid < ROWS_PB) {
        float st = ws[2 * tid] + ws[2 * tid + 1];
        float mm = fmaxf(wm[2 * tid], wm[2 * tid + 1]);
        float lse2 = mm + __log2f(st);
        float un = fmaf(-EPSLN2, lse2, eps_log_mu);
        int rw = row0 + tid;
        float old = g_u[rw];
        g_u[rw] = un;
        g_err[rw] = fabsf(un - old);
        urow[tid] = un * S_CONST;
    }
    __syncthreads();

    // ---- column phase: 2 cols/thread, two sweeps over smem av ----
    int j = 2 * tid;
    float vs0 = vsm[j], vs1 = vsm[j + 1];
    float mc0 = -INFINITY, mc1 = -INFINITY;
    #pragma unroll
    for (int rr = 0; rr < ROWS_PB; rr++) {
        float q = urow[rr];
        float2 a2 = *(const float2*)(av + rr * PP + j);
        mc0 = fmaxf(mc0, a2.x + (q - vs0));
        mc1 = fmaxf(mc1, a2.y + (q - vs1));
    }
    float vc0 = vs0 + mc0, vc1 = vs1 + mc1;
    float sc0 = 0.0f, sc1 = 0.0f;
    #pragma unroll
    for (int rr = 0; rr < ROWS_PB; rr++) {
        float q = urow[rr];
        float2 a2 = *(const float2*)(av + rr * PP + j);
        sc0 += ex2(a2.x + (q - vc0));
        sc1 += ex2(a2.y + (q - vc1));
    }
    size_t pb = (size_t)blk * PP + j;
    *(float2*)(g_pm + pb) = make_float2(mc0, mc1);
    *(float2*)(g_ps + pb) = make_float2(sc0, sc1);

    // ---- ticket ----
    __syncthreads();
    if (tid == 0) {
        __threadfence();
        s_oldb = atomicAdd(&g_cntb[it * BB + b], 1);
        s_olda = atomicAdd(&g_cnta[it], 1);
    }
    __syncthreads();
    int oldb = s_oldb, olda = s_olda;

    // last MSPLIT blocks of batch b merge 512 columns each (fixed fold order)
    if (oldb >= PBLKS - MSPLIT) {
        __threadfence();
        int rank = oldb - (PBLKS - MSPLIT);
        if (tid < 512) {
            int jj = rank * 512 + tid;
            const float* pm = g_pm + (size_t)(b * PBLKS) * PP + jj;
            const float* ps = g_ps + (size_t)(b * PBLKS) * PP + jj;
            float M0 = -INFINITY, S0 = 0.0f, M1 = -INFINITY, S1 = 0.0f;
            float M2 = -INFINITY, S2 = 0.0f, M3 = -INFINITY, S3 = 0.0f;
            #pragma unroll 8
            for (int q = 0; q < 32; q++) {
                lse_merge(M0, S0, pm[(size_t)q * PP],        ps[(size_t)q * PP]);
                lse_merge(M1, S1, pm[(size_t)(q + 32) * PP], ps[(size_t)(q + 32) * PP]);
                lse_merge(M2, S2, pm[(size_t)(q + 64) * PP], ps[(size_t)(q + 64) * PP]);
                lse_merge(M3, S3, pm[(size_t)(q + 96) * PP], ps[(size_t)(q + 96) * PP]);
            }
            lse_merge(M0, S0, M1, S1);
            lse_merge(M2, S2, M3, S3);
            lse_merge(M0, S0, M2, S2);
            float lse2 = M0 + __log2f(S0);
            g_v[b * PP + jj] = fmaf(-EPSLN2, lse2, eps_log_mu);
        }
    }

    // globally-last block computes the err sum and done flag (deterministic)
    if (olda == UVBLKS - 1) {
        __threadfence();
        float* red = av;   // reuse smem
        float ts = 0.0f;
        #pragma unroll
        for (int k = 0; k < NROWS / 1024; k++)
            ts += g_err[tid + k * 1024];
        __syncthreads();
        red[tid] = ts;
        __syncthreads();
        for (int st = 512; st > 0; st >>= 1) {
            if (tid < st) red[tid] += red[tid + st];
            __syncthreads();
        }
        if (tid == 0) g_done[it + 1] = (red[0] < thresh_tot) ? 1 : 0;
    }
}

// pi = exp2((u+v-C)*S); per-row partial of sum(pi*C)
__global__ __launch_bounds__(256) void kFinal(const float* __restrict__ C,
                                              float* __restrict__ pi) {
    __shared__ __align__(16) float wsm[PP];
    __shared__ float red[256];
    int row = blockIdx.x;
    int b = row >> 11;
    float ui = g_u[row];
    const float4* vb = (const float4*)(g_v + b * PP);
    for (int t = threadIdx.x; t < PP / 4; t += 256) {
        float4 v4 = vb[t];
        v4.x = (ui + v4.x) * S_CONST;
        v4.y = (ui + v4.y) * S_CONST;
        v4.z = (ui + v4.z) * S_CONST;
        v4.w = (ui + v4.w) * S_CONST;
        ((float4*)wsm)[t] = v4;
    }
    __syncthreads();
    const float4* Crow = (const float4*)(C + (size_t)row * PP);
    float4* prow = (float4*)(pi + (size_t)row * PP);
    const float4* ws4 = (const float4*)wsm;
    float local = 0.0f;
    #pragma unroll
    for (int k = 0; k < 2; k++) {
        int idx = threadIdx.x + k * 256;
        float4 c4 = Crow[idx];
        float4 w4 = ws4[idx];
        float4 p4;
        p4.x = ex2(fmaf(c4.x, -S_CONST, w4.x));
        p4.y = ex2(fmaf(c4.y, -S_CONST, w4.y));
        p4.z = ex2(fmaf(c4.z, -S_CONST, w4.z));
        p4.w = ex2(fmaf(c4.w, -S_CONST, w4.w));
        prow[idx] = p4;
        local = fmaf(p4.x, c4.x, local);
        local = fmaf(p4.y, c4.y, local);
        local = fmaf(p4.z, c4.z, local);
        local = fmaf(p4.w, c4.w, local);
    }
    red[threadIdx.x] = local;
    __syncthreads();
    for (int st = 128; st > 0; st >>= 1) {
        if (threadIdx.x < st) red[threadIdx.x] += red[threadIdx.x + st];
        __syncthreads();
    }
    if (threadIdx.x == 0) g_part[row] = red[0];
}

__global__ void kCost(float* __restrict__ cost) {
    __shared__ float red[256];
    int b = blockIdx.x;
    float t = 0.0f;
    #pragma unroll
    for (int k = 0; k < 8; k++)
        t += g_part[b * 2048 + threadIdx.x + k * 256];
    red[threadIdx.x] = t;
    __syncthreads();
    for (int st = 128; st > 0; st >>= 1) {
        if (threadIdx.x < st) red[threadIdx.x] += red[threadIdx.x + st];
        __syncthreads();
    }
    if (threadIdx.x == 0) cost[b] = red[0];
}

extern "C" void kernel_launch(void* const* d_in, const int* in_sizes, int n_in,
                              void* d_out, int out_size) {
    const float* x = (const float*)d_in[0];
    const float* y = (const float*)d_in[1];
    float* out  = (float*)d_out;
    float* cost = out;                        // 4
    float* pi   = out + 4;                    // 16777216
    float* C    = out + 4 + (size_t)NEL;      // 16777216

    float log_mu = logf(1.0f / 2048.0f + 1e-8f);   // == log_nu (P1==P2)
    float eps_log_mu = 0.1f * log_mu;
    float thresh_tot = 0.1f * (float)BB;           // global-sum form of err<0.1

    const int kuv_smem = (PP + ROWS_PB * PP + 32 + 32 + 16) * 4;  // ~136KB
    static int attr_set = 0;
    if (!attr_set) {
        cudaFuncSetAttribute(kUV, cudaFuncAttributeMaxDynamicSharedMemorySize,
                             kuv_smem);
        attr_set = 1;
    }

    kInit<<<(NROWS + 255) / 256, 256>>>();
    kNorm<<<2 * NROWS / 8, 256>>>(x, y);
    dim3 gC(PP / 64, PP / 64, BB);
    kC<<<gC, 256>>>(x, y, C);
    for (int it = 0; it < 100; it++) {
        kUV<<<UVBLKS, 1024, kuv_smem>>>(C, it, eps_log_mu, thresh_tot);
    }
    kFinal<<<NROWS, 256>>>(C, pi);
    kCost<<<BB, 256>>>(cost);
}